// round 2
// baseline (speedup 1.0000x reference)
#include <cuda_runtime.h>
#include <math.h>

// Problem constants (fixed instance)
#define NB    8          // batch
#define LQ    1024       // queries per batch
#define NQ    (NB*LQ)    // 8192 total queries
#define CDIM  256        // d_model
#define NH    8          // heads
#define NP    4          // points
#define HD    32         // head dim
#define IMH   128
#define IMW   128
#define HWPX  (IMH*IMW)  // 16384

// -------- scratch (static __device__; no allocation APIs allowed) --------
__device__ float g_Wcat[CDIM*128];        // [256,128]: cols 0..63 W_off, 64..95 W_attn, rest 0
__device__ float g_bcat[128];
__device__ float g_P[NQ*128];             // query @ Wcat + bcat
__device__ float g_AGG[NQ*NH*CDIM];       // aggregated 256-d memory per (q,h)  (64MB)
__device__ float g_WINB[NQ*NH];           // in-bounds weight sums (for b_value)
__device__ float g_X[NQ*CDIM];            // per-head projected output, concat

// ---------------------------------------------------------------------------
// k_pack: assemble [W_off | W_attn | 0] into one 256x128 matrix (+ bias)
// ---------------------------------------------------------------------------
__global__ void k_pack(const float* __restrict__ Woff, const float* __restrict__ boff,
                       const float* __restrict__ Wattn, const float* __restrict__ battn) {
    int t = blockIdx.x * blockDim.x + threadIdx.x;   // 0 .. 256*128-1
    int c = t >> 7, j = t & 127;
    float v = 0.f;
    if (j < 64)      v = Woff[c*64 + j];
    else if (j < 96) v = Wattn[c*32 + (j-64)];
    g_Wcat[c*128 + j] = v;
    if (c == 0) {
        float b = 0.f;
        if (j < 64)      b = boff[j];
        else if (j < 96) b = battn[j-64];
        g_bcat[j] = b;
    }
}

// ---------------------------------------------------------------------------
// k_gemm: C[M=8192, N] = A[8192,256] @ B[256,N] + bias.  64x64 tiles, 256 thr,
// 4x4 microtiles. N in {128, 256}.
// ---------------------------------------------------------------------------
__global__ __launch_bounds__(256) void k_gemm(const float* __restrict__ A,
                                              const float* __restrict__ B, int N,
                                              const float* __restrict__ bias,
                                              float* __restrict__ Cout) {
    __shared__ float As[64][33];
    __shared__ float Bs[32][64];
    int t  = threadIdx.x;
    int q0 = blockIdx.x * 64;
    int cb = blockIdx.y * 64;
    int tx = t & 15, ty = t >> 4;
    int c0 = tx * 4, r0 = ty * 4;
    float acc[4][4] = {};
    for (int k0 = 0; k0 < 256; k0 += 32) {
        #pragma unroll
        for (int i = 0; i < 8; i++) {
            int e = t + i*256; int row = e >> 5, kk = e & 31;
            As[row][kk] = A[(q0+row)*256 + k0 + kk];
        }
        #pragma unroll
        for (int i = 0; i < 8; i++) {
            int e = t + i*256; int kk = e >> 6, j = e & 63;
            Bs[kk][j] = B[(k0+kk)*N + cb + j];
        }
        __syncthreads();
        #pragma unroll
        for (int kk = 0; kk < 32; kk++) {
            float4 b4 = *(const float4*)&Bs[kk][c0];
            float a0 = As[r0+0][kk], a1 = As[r0+1][kk], a2 = As[r0+2][kk], a3 = As[r0+3][kk];
            acc[0][0] += a0*b4.x; acc[0][1] += a0*b4.y; acc[0][2] += a0*b4.z; acc[0][3] += a0*b4.w;
            acc[1][0] += a1*b4.x; acc[1][1] += a1*b4.y; acc[1][2] += a1*b4.z; acc[1][3] += a1*b4.w;
            acc[2][0] += a2*b4.x; acc[2][1] += a2*b4.y; acc[2][2] += a2*b4.z; acc[2][3] += a2*b4.w;
            acc[3][0] += a3*b4.x; acc[3][1] += a3*b4.y; acc[3][2] += a3*b4.z; acc[3][3] += a3*b4.w;
        }
        __syncthreads();
    }
    #pragma unroll
    for (int i = 0; i < 4; i++) {
        float4 o;
        o.x = acc[i][0] + bias[cb+c0+0];
        o.y = acc[i][1] + bias[cb+c0+1];
        o.z = acc[i][2] + bias[cb+c0+2];
        o.w = acc[i][3] + bias[cb+c0+3];
        *(float4*)&Cout[(q0+r0+i)*N + cb + c0] = o;
    }
}

// ---------------------------------------------------------------------------
// k_gather: one block (128 thr) per query.
//  - t<32 : softmax + pixel coords for (h,p)
//  - t<128: expand 128 bilinear corners, dedup rows into shared hash
//  - t<64 : accumulate distinct rows with float4 channels, 8 head accumulators
// ---------------------------------------------------------------------------
__global__ __launch_bounds__(128) void k_gather(const float* __restrict__ memory,
                                                const float* __restrict__ ref) {
    __shared__ int   s_key[256];
    __shared__ float s_w[256][NH];
    __shared__ int   s_list[128];
    __shared__ int   s_n;
    __shared__ float s_winb[NH];
    __shared__ float s_x[32], s_y[32], s_aw[32];

    int t = threadIdx.x;
    int q = blockIdx.x;
    int n = q >> 10;

    s_key[t] = -1; s_key[t+128] = -1;
    #pragma unroll
    for (int h = 0; h < NH; h++) { s_w[t][h] = 0.f; s_w[t+128][h] = 0.f; }
    if (t == 0) s_n = 0;
    if (t < NH) s_winb[t] = 0.f;

    if (t < 32) {   // per-(h,p) coords + softmax weight
        int h = t >> 2, p = t & 3;
        const float* Pq = &g_P[q*128];
        float rx = ref[q*2+0] * (float)IMW - 0.5f;
        float ry = ref[q*2+1] * (float)IMH - 0.5f;
        float a0 = Pq[64+h*4+0], a1 = Pq[64+h*4+1];
        float a2 = Pq[64+h*4+2], a3 = Pq[64+h*4+3];
        float m = fmaxf(fmaxf(a0,a1), fmaxf(a2,a3));
        float e0 = expf(a0-m), e1 = expf(a1-m), e2 = expf(a2-m), e3 = expf(a3-m);
        float inv = 1.f / (e0+e1+e2+e3);
        float ep = (p == 0) ? e0 : (p == 1) ? e1 : (p == 2) ? e2 : e3;
        s_x[t]  = rx + Pq[h*8 + p*2 + 0];
        s_y[t]  = ry + Pq[h*8 + p*2 + 1];
        s_aw[t] = ep * inv;
    }
    __syncthreads();

    {   // corner expansion + hash insert (all 128 threads, one corner each)
        int hp = t >> 2, corner = t & 3;
        int h = hp >> 2;
        float x  = s_x[hp], y = s_y[hp], aw = s_aw[hp];
        float fx0 = floorf(x), fy0 = floorf(y);
        int ix = (int)fx0 + (corner & 1);
        int iy = (int)fy0 + (corner >> 1);
        float fx = x - fx0, fy = y - fy0;
        float wx = (corner & 1) ? fx : (1.f - fx);
        float wy = (corner & 2) ? fy : (1.f - fy);
        float w = wx * wy * aw;
        if (ix >= 0 && ix < IMW && iy >= 0 && iy < IMH && w != 0.f) {
            int row = iy * IMW + ix;
            int slot = row & 255;
            while (true) {
                int prev = atomicCAS(&s_key[slot], -1, row);
                if (prev == -1 || prev == row) break;
                slot = (slot + 1) & 255;
            }
            atomicAdd(&s_w[slot][h], w);
            atomicAdd(&s_winb[h], w);
        }
    }
    __syncthreads();
    if (s_key[t]     != -1) { int pos = atomicAdd(&s_n, 1); s_list[pos] = t; }
    if (s_key[t+128] != -1) { int pos = atomicAdd(&s_n, 1); s_list[pos] = t+128; }
    __syncthreads();

    int nrows = s_n;
    const float* mem = memory + (size_t)n * HWPX * CDIM;

    if (t < 64) {
        int c = t * 4;                       // channel quad
        float4 acc[NH];
        #pragma unroll
        for (int h = 0; h < NH; h++) acc[h] = make_float4(0.f,0.f,0.f,0.f);

        int i = 0;
        for (; i + 1 < nrows; i += 2) {
            int s0 = s_list[i], s1 = s_list[i+1];
            float4 v0 = *(const float4*)&mem[(size_t)s_key[s0]*CDIM + c];
            float4 v1 = *(const float4*)&mem[(size_t)s_key[s1]*CDIM + c];
            #pragma unroll
            for (int h = 0; h < NH; h++) {
                float w0 = s_w[s0][h], w1 = s_w[s1][h];
                acc[h].x += w0*v0.x + w1*v1.x;
                acc[h].y += w0*v0.y + w1*v1.y;
                acc[h].z += w0*v0.z + w1*v1.z;
                acc[h].w += w0*v0.w + w1*v1.w;
            }
        }
        if (i < nrows) {
            int s0 = s_list[i];
            float4 v0 = *(const float4*)&mem[(size_t)s_key[s0]*CDIM + c];
            #pragma unroll
            for (int h = 0; h < NH; h++) {
                float w0 = s_w[s0][h];
                acc[h].x += w0*v0.x; acc[h].y += w0*v0.y;
                acc[h].z += w0*v0.z; acc[h].w += w0*v0.w;
            }
        }
        #pragma unroll
        for (int h = 0; h < NH; h++)
            *(float4*)&g_AGG[((size_t)(q*NH) + h)*CDIM + c] = acc[h];
    }
    if (t < NH) g_WINB[q*NH + t] = s_winb[t];
}

// ---------------------------------------------------------------------------
// k_headproj: X[q, h*32+j] = AGG[q,h,:] . Wv[:, h*32+j] + b_value*WINB
// 64 queries x 32 cols per block (one head), 128 threads, 4x4 microtiles.
// ---------------------------------------------------------------------------
__global__ __launch_bounds__(128) void k_headproj(const float* __restrict__ Wv,
                                                  const float* __restrict__ bv) {
    __shared__ float As[64][33];
    __shared__ float Bs[32][32];
    int t  = threadIdx.x;
    int q0 = blockIdx.x * 64;
    int h  = blockIdx.y;
    int tx = t & 7, ty = t >> 3;
    int c0 = tx * 4, r0 = ty * 4;
    float acc[4][4] = {};
    for (int k0 = 0; k0 < 256; k0 += 32) {
        #pragma unroll
        for (int i = 0; i < 16; i++) {
            int e = t + i*128; int row = e >> 5, kk = e & 31;
            As[row][kk] = g_AGG[((q0+row)*NH + h)*CDIM + k0 + kk];
        }
        #pragma unroll
        for (int i = 0; i < 8; i++) {
            int e = t + i*128; int kk = e >> 5, j = e & 31;
            Bs[kk][j] = Wv[(k0+kk)*CDIM + h*HD + j];
        }
        __syncthreads();
        #pragma unroll
        for (int kk = 0; kk < 32; kk++) {
            float4 b4 = *(const float4*)&Bs[kk][c0];
            float a0 = As[r0+0][kk], a1 = As[r0+1][kk], a2 = As[r0+2][kk], a3 = As[r0+3][kk];
            acc[0][0] += a0*b4.x; acc[0][1] += a0*b4.y; acc[0][2] += a0*b4.z; acc[0][3] += a0*b4.w;
            acc[1][0] += a1*b4.x; acc[1][1] += a1*b4.y; acc[1][2] += a1*b4.z; acc[1][3] += a1*b4.w;
            acc[2][0] += a2*b4.x; acc[2][1] += a2*b4.y; acc[2][2] += a2*b4.z; acc[2][3] += a2*b4.w;
            acc[3][0] += a3*b4.x; acc[3][1] += a3*b4.y; acc[3][2] += a3*b4.z; acc[3][3] += a3*b4.w;
        }
        __syncthreads();
    }
    #pragma unroll
    for (int i = 0; i < 4; i++) {
        float wb = g_WINB[(q0+r0+i)*NH + h];
        float4 o;
        o.x = acc[i][0] + bv[h*HD + c0+0]*wb;
        o.y = acc[i][1] + bv[h*HD + c0+1]*wb;
        o.z = acc[i][2] + bv[h*HD + c0+2]*wb;
        o.w = acc[i][3] + bv[h*HD + c0+3]*wb;
        *(float4*)&g_X[(q0+r0+i)*CDIM + h*HD + c0] = o;
    }
}

// ---------------------------------------------------------------------------
extern "C" void kernel_launch(void* const* d_in, const int* in_sizes, int n_in,
                              void* d_out, int out_size) {
    const float* query  = (const float*)d_in[0];
    const float* memory = (const float*)d_in[1];
    const float* refpts = (const float*)d_in[2];
    const float* Wv     = (const float*)d_in[3];
    const float* bv     = (const float*)d_in[4];
    const float* Woff   = (const float*)d_in[5];
    const float* boff   = (const float*)d_in[6];
    const float* Wattn  = (const float*)d_in[7];
    const float* battn  = (const float*)d_in[8];
    const float* Wout   = (const float*)d_in[9];
    const float* bout   = (const float*)d_in[10];
    float* out = (float*)d_out;

    float *pWcat, *pbcat, *pP, *pX;
    cudaGetSymbolAddress((void**)&pWcat, g_Wcat);
    cudaGetSymbolAddress((void**)&pbcat, g_bcat);
    cudaGetSymbolAddress((void**)&pP,    g_P);
    cudaGetSymbolAddress((void**)&pX,    g_X);

    // 1. pack offset/attn weight matrices
    k_pack<<<(CDIM*128)/256, 256>>>(Woff, boff, Wattn, battn);
    // 2. P = query @ Wcat + bcat          [8192 x 128]
    k_gemm<<<dim3(NQ/64, 2), 256>>>(query, pWcat, 128, pbcat, pP);
    // 3. fused sampler + dedup gather + per-head aggregation of raw memory
    k_gather<<<NQ, 128>>>(memory, refpts);
    // 4. per-head projection: X = blockdiag(AGG @ Wv_h) + b_value*winb
    k_headproj<<<dim3(NQ/64, NH), 128>>>(Wv, bv);
    // 5. out = X @ W_out + b_out          [8192 x 256]
    k_gemm<<<dim3(NQ/64, 4), 256>>>(pX, Wout, 256, bout, out);
}